// round 1
// baseline (speedup 1.0000x reference)
#include <cuda_runtime.h>
#include <cuda_bf16.h>
#include <math.h>

// ---------------- problem constants ----------------
#define BATCH   4
#define SEQ     2048
#define DMODEL  768
#define DSTATE  16
#define DCONV   4
#define HEADDIM 64
#define DINNER  1536
#define NHEADS  24
#define CONVDIM 1568                 // DINNER + 2*DSTATE
#define DPROJ   3128                 // 2*DINNER + 2*DSTATE + NHEADS
#define NTOK    (BATCH*SEQ)          // 8192
#define DFFN    3072

// ---------------- scratch (device globals; no allocation allowed) ----------------
__device__ float g_xn  [(size_t)NTOK*DMODEL];
__device__ float g_proj[(size_t)NTOK*DPROJ];
__device__ float g_conv[(size_t)NTOK*CONVDIM];
__device__ float g_dt  [(size_t)NTOK*NHEADS];
__device__ float g_dA  [(size_t)NTOK*NHEADS];
__device__ float g_y   [(size_t)NTOK*DINNER];
__device__ float g_bi  [(size_t)NTOK*DINNER];
__device__ float g_ffn [(size_t)NTOK*DFFN];
__device__ float g_h2  [(size_t)NTOK*DMODEL];

// ---------------- helpers ----------------
__device__ __forceinline__ float gelu_exact(float x) {
    return 0.5f * x * (1.0f + erff(x * 0.70710678118654752f));
}
__device__ __forceinline__ float silu(float x) {
    return x / (1.0f + expf(-x));
}

__device__ float block_reduce_sum(float v) {
    __shared__ float sh[32];
    __shared__ float tot;
    int lane = threadIdx.x & 31, wid = threadIdx.x >> 5;
    #pragma unroll
    for (int m = 16; m >= 1; m >>= 1) v += __shfl_xor_sync(0xffffffffu, v, m);
    if (lane == 0) sh[wid] = v;
    __syncthreads();
    int nw = blockDim.x >> 5;
    v = (threadIdx.x < nw) ? sh[threadIdx.x] : 0.f;
    if (wid == 0) {
        #pragma unroll
        for (int m = 16; m >= 1; m >>= 1) v += __shfl_xor_sync(0xffffffffu, v, m);
        if (lane == 0) tot = v;
    }
    __syncthreads();
    return tot;
}

// ---------------- layernorm (cols = 768), optional residual add ----------------
__global__ __launch_bounds__(256) void layernorm_kernel(
    const float* __restrict__ x, const float* __restrict__ add,
    const float* __restrict__ w, const float* __restrict__ b,
    float* __restrict__ out)
{
    int row = blockIdx.x;
    int tid = threadIdx.x;
    const size_t base = (size_t)row * DMODEL;
    float v[3];
    float s = 0.f;
    #pragma unroll
    for (int i = 0; i < 3; i++) {
        int c = tid + i * 256;
        float t = x[base + c];
        if (add) t += add[base + c];
        v[i] = t; s += t;
    }
    float mean = block_reduce_sum(s) * (1.0f / DMODEL);
    float sq = 0.f;
    #pragma unroll
    for (int i = 0; i < 3; i++) { float d = v[i] - mean; sq += d * d; }
    float var = block_reduce_sum(sq) * (1.0f / DMODEL);
    float rstd = rsqrtf(var + 1e-5f);
    #pragma unroll
    for (int i = 0; i < 3; i++) {
        int c = tid + i * 256;
        out[base + c] = (v[i] - mean) * rstd * w[c] + b[c];
    }
}

// ---------------- SGEMM: C[M,N] = act(A[M,K] @ W[K,N] + bias) ----------------
// 128x128 tile, BK=8, 256 threads, 8x8 per thread.
#define BM 128
#define BN 128
#define BKK 8
template<int ACT, bool HAS_BIAS>
__global__ __launch_bounds__(256) void sgemm_kernel(
    const float* __restrict__ A, const float* __restrict__ W,
    const float* __restrict__ bias, float* __restrict__ C,
    int M, int N, int K, int ldc, int coff)
{
    __shared__ float As[BKK][BM + 4];
    __shared__ float Ws[BKK][BN];
    int tid = threadIdx.x;
    int m0 = blockIdx.y * BM;
    int n0 = blockIdx.x * BN;

    int arow = tid >> 1;
    int acol = (tid & 1) * 4;
    int wrow = tid >> 5;
    int wcol = (tid & 31) * 4;

    int ty = tid >> 4, tx = tid & 15;
    float acc[8][8];
    #pragma unroll
    for (int i = 0; i < 8; i++)
        #pragma unroll
        for (int j = 0; j < 8; j++) acc[i][j] = 0.f;

    for (int k0 = 0; k0 < K; k0 += BKK) {
        float4 av = make_float4(0.f, 0.f, 0.f, 0.f);
        if (m0 + arow < M)
            av = *(const float4*)(A + (size_t)(m0 + arow) * K + k0 + acol);
        As[acol + 0][arow] = av.x;
        As[acol + 1][arow] = av.y;
        As[acol + 2][arow] = av.z;
        As[acol + 3][arow] = av.w;

        float4 wv = make_float4(0.f, 0.f, 0.f, 0.f);
        if (n0 + wcol < N)
            wv = *(const float4*)(W + (size_t)(k0 + wrow) * N + n0 + wcol);
        *(float4*)&Ws[wrow][wcol] = wv;
        __syncthreads();

        #pragma unroll
        for (int k = 0; k < BKK; k++) {
            float ra[8], rb[8];
            #pragma unroll
            for (int i = 0; i < 8; i++) ra[i] = As[k][ty * 8 + i];
            #pragma unroll
            for (int j = 0; j < 8; j++) rb[j] = Ws[k][tx * 8 + j];
            #pragma unroll
            for (int i = 0; i < 8; i++)
                #pragma unroll
                for (int j = 0; j < 8; j++)
                    acc[i][j] += ra[i] * rb[j];
        }
        __syncthreads();
    }

    #pragma unroll
    for (int i = 0; i < 8; i++) {
        int row = m0 + ty * 8 + i;
        if (row >= M) continue;
        #pragma unroll
        for (int j = 0; j < 8; j++) {
            int col = n0 + tx * 8 + j;
            if (col >= N) continue;
            float v = acc[i][j];
            if (HAS_BIAS) v += bias[col];
            if (ACT == 1) v = gelu_exact(v);
            C[(size_t)row * ldc + coff + col] = v;
        }
    }
}

// ---------------- dt / dA ----------------
__global__ void dtda_kernel(const float* __restrict__ proj,
                            const float* __restrict__ dt_bias,
                            const float* __restrict__ A_log,
                            float* __restrict__ dt, float* __restrict__ dA)
{
    int idx = blockIdx.x * blockDim.x + threadIdx.x;
    if (idx >= NTOK * NHEADS) return;
    int h = idx % NHEADS;
    int j = idx / NHEADS;
    float raw = proj[(size_t)j * DPROJ + (DINNER + CONVDIM) + h] + dt_bias[h];
    float d = (raw > 20.f) ? raw : log1pf(expf(raw));
    float A = -expf(A_log[h]);
    dt[idx] = d;
    dA[idx] = expf(d * A);
}

// ---------------- causal (or anticausal) depthwise conv + silu ----------------
__global__ void conv_kernel(const float* __restrict__ proj,
                            const float* __restrict__ cw,
                            const float* __restrict__ cb,
                            float* __restrict__ out, int reverse)
{
    int idx = blockIdx.x * blockDim.x + threadIdx.x;
    if (idx >= NTOK * CONVDIM) return;
    int c = idx % CONVDIM;
    int row = idx / CONVDIM;
    int t = row % SEQ;
    int brow = row - t;
    float acc = cb[c];
    #pragma unroll
    for (int k = 0; k < DCONV; k++) {
        int tt = reverse ? (t + (DCONV - 1) - k) : (t + k - (DCONV - 1));
        if (tt >= 0 && tt < SEQ)
            acc += cw[c * DCONV + k] * proj[(size_t)(brow + tt) * DPROJ + DINNER + c];
    }
    out[idx] = silu(acc);
}

// ---------------- selective scan: one CTA per (batch, head) ----------------
#define SCHUNK 64
__global__ __launch_bounds__(512) void scan_kernel(
    const float* __restrict__ conv, const float* __restrict__ dt,
    const float* __restrict__ dA, const float* __restrict__ Dp,
    float* __restrict__ y, int reverse)
{
    int b = blockIdx.x / NHEADS;
    int h = blockIdx.x % NHEADS;
    int tid = threadIdx.x;
    int n  = tid & 15;    // state index
    int pp = tid >> 4;    // 0..31 ; handles p = pp and p = pp+32

    __shared__ float sx[SCHUNK][HEADDIM];
    __shared__ float sB[SCHUNK][DSTATE];
    __shared__ float sC[SCHUNK][DSTATE];
    __shared__ float sdt[SCHUNK];
    __shared__ float sdA[SCHUNK];

    float h0 = 0.f, h1 = 0.f;
    const float Dv = Dp[h];

    for (int c0 = 0; c0 < SEQ; c0 += SCHUNK) {
        #pragma unroll
        for (int i = 0; i < 8; i++) {
            int idx = i * 512 + tid;
            int s = idx >> 6, p = idx & 63;
            int t = reverse ? (SEQ - 1 - (c0 + s)) : (c0 + s);
            sx[s][p] = conv[((size_t)(b * SEQ + t)) * CONVDIM + h * HEADDIM + p];
        }
        #pragma unroll
        for (int i = 0; i < 2; i++) {
            int idx = i * 512 + tid;
            int s = idx >> 4, nn = idx & 15;
            int t = reverse ? (SEQ - 1 - (c0 + s)) : (c0 + s);
            size_t base = ((size_t)(b * SEQ + t)) * CONVDIM;
            sB[s][nn] = conv[base + DINNER + nn];
            sC[s][nn] = conv[base + DINNER + DSTATE + nn];
        }
        if (tid < SCHUNK) {
            int t = reverse ? (SEQ - 1 - (c0 + tid)) : (c0 + tid);
            sdt[tid] = dt[(size_t)(b * SEQ + t) * NHEADS + h];
            sdA[tid] = dA[(size_t)(b * SEQ + t) * NHEADS + h];
        }
        __syncthreads();

        #pragma unroll 4
        for (int s = 0; s < SCHUNK; s++) {
            float dAv = sdA[s], dtv = sdt[s];
            float Bn = sB[s][n], Cn = sC[s][n];
            float x0 = sx[s][pp], x1 = sx[s][pp + 32];
            h0 = h0 * dAv + (dtv * x0) * Bn;
            h1 = h1 * dAv + (dtv * x1) * Bn;
            float y0 = h0 * Cn, y1 = h1 * Cn;
            #pragma unroll
            for (int m = 8; m >= 1; m >>= 1) {
                y0 += __shfl_xor_sync(0xffffffffu, y0, m);
                y1 += __shfl_xor_sync(0xffffffffu, y1, m);
            }
            if (n == 0) {
                int t = reverse ? (SEQ - 1 - (c0 + s)) : (c0 + s);
                size_t o = ((size_t)(b * SEQ + t)) * DINNER + h * HEADDIM;
                y[o + pp]      = y0 + Dv * x0;
                y[o + pp + 32] = y1 + Dv * x1;
            }
        }
        __syncthreads();
    }
}

// ---------------- gate (y * silu(z)) + grouped RMSNorm (over 1536) ----------------
__global__ __launch_bounds__(256) void gate_rmsnorm_kernel(
    const float* __restrict__ proj, const float* __restrict__ y_in,
    const float* __restrict__ norm_w, float* __restrict__ y_out)
{
    int row = blockIdx.x;
    int tid = threadIdx.x;
    float v[6];
    float ss = 0.f;
    #pragma unroll
    for (int i = 0; i < 6; i++) {
        int c = tid + i * 256;
        float z  = proj[(size_t)row * DPROJ + c];
        float yv = y_in[(size_t)row * DINNER + c];
        float t = yv * silu(z);
        v[i] = t; ss += t * t;
    }
    float tot = block_reduce_sum(ss);
    float rs = rsqrtf(tot * (1.0f / DINNER) + 1e-5f);
    #pragma unroll
    for (int i = 0; i < 6; i++) {
        int c = tid + i * 256;
        y_out[(size_t)row * DINNER + c] = v[i] * rs * norm_w[c];
    }
}

// ---------------- host-side input binding by element count ----------------
static const float* pick(void* const* d_in, const int* sz, int n_in, int count, int occ) {
    int seen = 0;
    for (int i = 0; i < n_in; i++) {
        if (sz[i] == count) {
            if (seen == occ) return (const float*)d_in[i];
            seen++;
        }
    }
    return nullptr;
}

extern "C" void kernel_launch(void* const* d_in, const int* in_sizes, int n_in,
                              void* d_out, int out_size)
{
    const float* x      = pick(d_in, in_sizes, n_in, NTOK * DMODEL, 0);       // 6291456
    const float* ln1_w  = pick(d_in, in_sizes, n_in, 768, 0);
    const float* ln1_b  = pick(d_in, in_sizes, n_in, 768, 1);
    const float* ln2_w  = pick(d_in, in_sizes, n_in, 768, 2);
    const float* ln2_b  = pick(d_in, in_sizes, n_in, 768, 3);
    const float* ffn_b2 = pick(d_in, in_sizes, n_in, 768, 4);
    const float* ffn_w1 = pick(d_in, in_sizes, n_in, DINNER * DFFN, 0);       // 4718592
    const float* ffn_b1 = pick(d_in, in_sizes, n_in, DFFN, 0);                // 3072
    const float* ffn_w2 = pick(d_in, in_sizes, n_in, DFFN * DMODEL, 0);       // 2359296

    const float* in_w[2]    = { pick(d_in, in_sizes, n_in, DMODEL * DPROJ, 0),
                                pick(d_in, in_sizes, n_in, DMODEL * DPROJ, 1) };   // 2402304
    const float* conv_w[2]  = { pick(d_in, in_sizes, n_in, CONVDIM * DCONV, 0),
                                pick(d_in, in_sizes, n_in, CONVDIM * DCONV, 1) };  // 6272
    const float* conv_b[2]  = { pick(d_in, in_sizes, n_in, CONVDIM, 0),
                                pick(d_in, in_sizes, n_in, CONVDIM, 1) };          // 1568
    const float* dt_bias[2] = { pick(d_in, in_sizes, n_in, NHEADS, 0),
                                pick(d_in, in_sizes, n_in, NHEADS, 3) };
    const float* A_log[2]   = { pick(d_in, in_sizes, n_in, NHEADS, 1),
                                pick(d_in, in_sizes, n_in, NHEADS, 4) };
    const float* Dp[2]      = { pick(d_in, in_sizes, n_in, NHEADS, 2),
                                pick(d_in, in_sizes, n_in, NHEADS, 5) };
    const float* norm_w[2]  = { pick(d_in, in_sizes, n_in, DINNER, 0),
                                pick(d_in, in_sizes, n_in, DINNER, 1) };
    const float* out_w[2]   = { pick(d_in, in_sizes, n_in, DINNER * DMODEL, 0),
                                pick(d_in, in_sizes, n_in, DINNER * DMODEL, 1) }; // 1179648

    float *p_xn, *p_proj, *p_conv, *p_dt, *p_dA, *p_y, *p_bi, *p_ffn, *p_h2;
    cudaGetSymbolAddress((void**)&p_xn,   g_xn);
    cudaGetSymbolAddress((void**)&p_proj, g_proj);
    cudaGetSymbolAddress((void**)&p_conv, g_conv);
    cudaGetSymbolAddress((void**)&p_dt,   g_dt);
    cudaGetSymbolAddress((void**)&p_dA,   g_dA);
    cudaGetSymbolAddress((void**)&p_y,    g_y);
    cudaGetSymbolAddress((void**)&p_bi,   g_bi);
    cudaGetSymbolAddress((void**)&p_ffn,  g_ffn);
    cudaGetSymbolAddress((void**)&p_h2,   g_h2);

    float* out = (float*)d_out;

    // 1) LN1
    layernorm_kernel<<<NTOK, 256>>>(x, nullptr, ln1_w, ln1_b, p_xn);

    // 2) two mamba directions
    for (int dir = 0; dir < 2; dir++) {
        int rev = dir;  // dir 0 = forward, dir 1 = reverse-time
        // in_proj: [8192,768] @ [768,3128]
        {
            dim3 grid((DPROJ + BN - 1) / BN, (NTOK + BM - 1) / BM);
            sgemm_kernel<0, false><<<grid, 256>>>(p_xn, in_w[dir], nullptr, p_proj,
                                                  NTOK, DPROJ, DMODEL, DPROJ, 0);
        }
        // dt / dA
        dtda_kernel<<<(NTOK * NHEADS + 255) / 256, 256>>>(p_proj, dt_bias[dir], A_log[dir], p_dt, p_dA);
        // conv + silu
        conv_kernel<<<(NTOK * CONVDIM + 255) / 256, 256>>>(p_proj, conv_w[dir], conv_b[dir], p_conv, rev);
        // selective scan
        scan_kernel<<<BATCH * NHEADS, 512>>>(p_conv, p_dt, p_dA, Dp[dir], p_y, rev);
        // gate + rmsnorm
        gate_rmsnorm_kernel<<<NTOK, 256>>>(p_proj, p_y, norm_w[dir], p_y);
        // out_proj into g_bi at column offset dir*768 : [8192,1536] @ [1536,768]
        {
            dim3 grid((DMODEL + BN - 1) / BN, (NTOK + BM - 1) / BM);
            sgemm_kernel<0, false><<<grid, 256>>>(p_y, out_w[dir], nullptr, p_bi,
                                                  NTOK, DMODEL, DINNER, DINNER, dir * DMODEL);
        }
    }

    // 3) FFN1: gelu(bi @ w1 + b1)
    {
        dim3 grid((DFFN + BN - 1) / BN, (NTOK + BM - 1) / BM);
        sgemm_kernel<1, true><<<grid, 256>>>(p_bi, ffn_w1, ffn_b1, p_ffn,
                                             NTOK, DFFN, DINNER, DFFN, 0);
    }
    // 4) FFN2: gelu(h @ w2 + b2)
    {
        dim3 grid((DMODEL + BN - 1) / BN, (NTOK + BM - 1) / BM);
        sgemm_kernel<1, true><<<grid, 256>>>(p_ffn, ffn_w2, ffn_b2, p_h2,
                                             NTOK, DMODEL, DFFN, DMODEL, 0);
    }
    // 5) out = LN2(x + h)
    layernorm_kernel<<<NTOK, 256>>>(x, p_h2, ln2_w, ln2_b, out);
}

// round 5
// speedup vs baseline: 3.9451x; 3.9451x over previous
#include <cuda_runtime.h>
#include <cuda_fp16.h>
#include <cuda_pipeline.h>
#include <mma.h>
#include <math.h>

using namespace nvcuda;

// ---------------- problem constants ----------------
#define BATCH   4
#define SEQ     2048
#define DMODEL  768
#define DSTATE  16
#define DCONV   4
#define HEADDIM 64
#define DINNER  1536
#define NHEADS  24
#define CONVDIM 1568
#define DPROJ   3128
#define DPROJP  3200
#define NTOK    (BATCH*SEQ)
#define DFFN    3072

// ---------------- scratch (device globals; no allocation allowed) ----------------
__device__ float g_proj[(size_t)NTOK*DPROJP];
__device__ float g_conv[(size_t)NTOK*CONVDIM];
__device__ float g_dt  [(size_t)NTOK*NHEADS];
__device__ float g_dA  [(size_t)NTOK*NHEADS];
__device__ float g_y   [(size_t)NTOK*DINNER];
__device__ float g_bi  [(size_t)NTOK*DINNER];
__device__ float g_ffn [(size_t)NTOK*DFFN];
__device__ float g_h2  [(size_t)NTOK*DMODEL];

// fp16 activation buffers
__device__ __half h_xn [(size_t)NTOK*DMODEL];
__device__ __half h_bi [(size_t)NTOK*DINNER];
__device__ __half h_ffn[(size_t)NTOK*DFFN];
__device__ __half h_yg [(size_t)NTOK*DINNER];

// fp16 weight buffers
__device__ __half hw_in0 [(size_t)DMODEL*DPROJ];
__device__ __half hw_in1 [(size_t)DMODEL*DPROJ];
__device__ __half hw_out0[(size_t)DINNER*DMODEL];
__device__ __half hw_out1[(size_t)DINNER*DMODEL];
__device__ __half hw_f1  [(size_t)DINNER*DFFN];
__device__ __half hw_f2  [(size_t)DFFN*DMODEL];

// ---------------- helpers ----------------
__device__ __forceinline__ float gelu_exact(float x) {
    return 0.5f * x * (1.0f + erff(x * 0.70710678118654752f));
}
__device__ __forceinline__ float silu(float x) {
    return x / (1.0f + expf(-x));
}

__device__ float block_reduce_sum(float v) {
    __shared__ float sh[32];
    __shared__ float tot;
    int lane = threadIdx.x & 31, wid = threadIdx.x >> 5;
    #pragma unroll
    for (int m = 16; m >= 1; m >>= 1) v += __shfl_xor_sync(0xffffffffu, v, m);
    if (lane == 0) sh[wid] = v;
    __syncthreads();
    int nw = blockDim.x >> 5;
    v = (threadIdx.x < nw) ? sh[threadIdx.x] : 0.f;
    if (wid == 0) {
        #pragma unroll
        for (int m = 16; m >= 1; m >>= 1) v += __shfl_xor_sync(0xffffffffu, v, m);
        if (lane == 0) tot = v;
    }
    __syncthreads();
    return tot;
}

// ---------------- fp32 -> fp16 convert ----------------
__global__ void f2h_kernel(const float* __restrict__ src, __half* __restrict__ dst, int n4)
{
    int i = blockIdx.x * blockDim.x + threadIdx.x;
    if (i >= n4) return;
    float4 v = ((const float4*)src)[i];
    ((__half2*)dst)[i * 2 + 0] = __floats2half2_rn(v.x, v.y);
    ((__half2*)dst)[i * 2 + 1] = __floats2half2_rn(v.z, v.w);
}

// ---------------- bias + gelu postproc (fp32 in; fp32 and/or fp16 out) ----------------
__global__ void bias_gelu_kernel(const float* __restrict__ in,
                                 const float* __restrict__ bias,
                                 float* __restrict__ outf,
                                 __half* __restrict__ outh,
                                 int ncols, int ntotal)
{
    int i = blockIdx.x * blockDim.x + threadIdx.x;
    if (i >= ntotal) return;
    int c = i % ncols;
    float v = gelu_exact(in[i] + bias[c]);
    if (outf) outf[i] = v;
    if (outh) outh[i] = __float2half_rn(v);
}

// ---------------- layernorm (cols = 768), optional residual add ----------------
__global__ __launch_bounds__(256) void layernorm_kernel(
    const float* __restrict__ x, const float* __restrict__ add,
    const float* __restrict__ w, const float* __restrict__ b,
    float* __restrict__ out, __half* __restrict__ outh)
{
    int row = blockIdx.x;
    int tid = threadIdx.x;
    const size_t base = (size_t)row * DMODEL;
    float v[3];
    float s = 0.f;
    #pragma unroll
    for (int i = 0; i < 3; i++) {
        int c = tid + i * 256;
        float t = x[base + c];
        if (add) t += add[base + c];
        v[i] = t; s += t;
    }
    float mean = block_reduce_sum(s) * (1.0f / DMODEL);
    float sq = 0.f;
    #pragma unroll
    for (int i = 0; i < 3; i++) { float d = v[i] - mean; sq += d * d; }
    float var = block_reduce_sum(sq) * (1.0f / DMODEL);
    float rstd = rsqrtf(var + 1e-5f);
    #pragma unroll
    for (int i = 0; i < 3; i++) {
        int c = tid + i * 256;
        float r = (v[i] - mean) * rstd * w[c] + b[c];
        if (out)  out[base + c] = r;
        if (outh) outh[base + c] = __float2half_rn(r);
    }
}

// ---------------- WMMA HGEMM: C[M,N](fp32) = A[M,K](fp16) @ W[K,N](fp16) ----------------
// 128x128 tile, BK=32, 256 threads / 8 warps, warp tile 32x64 (2x4 wmma frags).
#define BM 128
#define BN 128
#define BK 32
#define ASTR 40
#define BSTR 136

__device__ __forceinline__ void hgemm_stage(
    const __half* __restrict__ A, const __half* __restrict__ W,
    int K, int N, int m0, int n0, int k0,
    __half* Asb, __half* Bsb, int tid)
{
    #pragma unroll
    for (int i = 0; i < 2; i++) {
        int c = tid + i * 256;
        int row = c >> 2;
        int col8 = (c & 3) << 3;
        const __half* src = A + (size_t)(m0 + row) * K + k0 + col8;
        __pipeline_memcpy_async(Asb + row * ASTR + col8, src, 16);
    }
    #pragma unroll
    for (int i = 0; i < 2; i++) {
        int c = tid + i * 256;
        int row = c >> 4;
        int col8 = (c & 15) << 3;
        __half* d = Bsb + row * BSTR + col8;
        if (n0 + col8 < N) {
            const __half* src = W + (size_t)(k0 + row) * N + n0 + col8;
            __pipeline_memcpy_async(d, src, 16);
        } else {
            *(float4*)d = make_float4(0.f, 0.f, 0.f, 0.f);
        }
    }
    __pipeline_commit();
}

__global__ __launch_bounds__(256) void hgemm_wmma(
    const __half* __restrict__ A, const __half* __restrict__ W,
    float* __restrict__ C,
    int M, int N, int K, int ldc, int coff)
{
    __shared__ __half As[2][BM * ASTR];
    __shared__ __half Bs[2][BK * BSTR];

    const int tid  = threadIdx.x;
    const int wid  = tid >> 5;
    const int warp_m = wid & 3;
    const int warp_n = wid >> 2;
    const int m0 = blockIdx.y * BM;
    const int n0 = blockIdx.x * BN;

    wmma::fragment<wmma::accumulator, 16, 16, 16, float> cfr[2][4];
    #pragma unroll
    for (int i = 0; i < 2; i++) {
        #pragma unroll
        for (int j = 0; j < 4; j++) wmma::fill_fragment(cfr[i][j], 0.0f);
    }

    const int nK = K / BK;
    hgemm_stage(A, W, K, N, m0, n0, 0, As[0], Bs[0], tid);
    int buf = 0;

    for (int kt = 0; kt < nK; kt++) {
        __pipeline_wait_prior(0);
        __syncthreads();
        if (kt + 1 < nK) {
            hgemm_stage(A, W, K, N, m0, n0, (kt + 1) * BK, As[buf ^ 1], Bs[buf ^ 1], tid);
        }

        #pragma unroll
        for (int kc = 0; kc < BK; kc += 16) {
            wmma::fragment<wmma::matrix_a, 16, 16, 16, __half, wmma::row_major> afr[2];
            wmma::fragment<wmma::matrix_b, 16, 16, 16, __half, wmma::row_major> bfr[4];
            #pragma unroll
            for (int i = 0; i < 2; i++) {
                wmma::load_matrix_sync(afr[i], &As[buf][(warp_m * 32 + i * 16) * ASTR + kc], ASTR);
            }
            #pragma unroll
            for (int j = 0; j < 4; j++) {
                wmma::load_matrix_sync(bfr[j], &Bs[buf][kc * BSTR + warp_n * 64 + j * 16], BSTR);
            }
            #pragma unroll
            for (int i = 0; i < 2; i++) {
                #pragma unroll
                for (int j = 0; j < 4; j++) {
                    wmma::mma_sync(cfr[i][j], afr[i], bfr[j], cfr[i][j]);
                }
            }
        }
        buf ^= 1;
    }

    #pragma unroll
    for (int i = 0; i < 2; i++) {
        #pragma unroll
        for (int j = 0; j < 4; j++) {
            int row = m0 + warp_m * 32 + i * 16;
            int col = n0 + warp_n * 64 + j * 16;
            wmma::store_matrix_sync(&C[(size_t)row * ldc + coff + col], cfr[i][j], ldc, wmma::mem_row_major);
        }
    }
}

// ---------------- dt / dA ----------------
__global__ void dtda_kernel(const float* __restrict__ proj,
                            const float* __restrict__ dt_bias,
                            const float* __restrict__ A_log,
                            float* __restrict__ dt, float* __restrict__ dA)
{
    int idx = blockIdx.x * blockDim.x + threadIdx.x;
    if (idx >= NTOK * NHEADS) return;
    int h = idx % NHEADS;
    int j = idx / NHEADS;
    float raw = proj[(size_t)j * DPROJP + (DINNER + CONVDIM) + h] + dt_bias[h];
    float d = (raw > 20.f) ? raw : log1pf(expf(raw));
    float A = -expf(A_log[h]);
    dt[idx] = d;
    dA[idx] = expf(d * A);
}

// ---------------- causal (or anticausal) depthwise conv + silu ----------------
__global__ void conv_kernel(const float* __restrict__ proj,
                            const float* __restrict__ cw,
                            const float* __restrict__ cb,
                            float* __restrict__ out, int reverse)
{
    int idx = blockIdx.x * blockDim.x + threadIdx.x;
    if (idx >= NTOK * CONVDIM) return;
    int c = idx % CONVDIM;
    int row = idx / CONVDIM;
    int t = row % SEQ;
    int brow = row - t;
    float acc = cb[c];
    #pragma unroll
    for (int k = 0; k < DCONV; k++) {
        int tt = reverse ? (t + (DCONV - 1) - k) : (t + k - (DCONV - 1));
        if (tt >= 0 && tt < SEQ)
            acc += cw[c * DCONV + k] * proj[(size_t)(brow + tt) * DPROJP + DINNER + c];
    }
    out[idx] = silu(acc);
}

// ---------------- selective scan: one CTA per (batch, head) ----------------
#define SCHUNK 64
__global__ __launch_bounds__(512) void scan_kernel(
    const float* __restrict__ conv, const float* __restrict__ dt,
    const float* __restrict__ dA, const float* __restrict__ Dp,
    float* __restrict__ y, int reverse)
{
    int b = blockIdx.x / NHEADS;
    int h = blockIdx.x % NHEADS;
    int tid = threadIdx.x;
    int n  = tid & 15;
    int pp = tid >> 4;

    __shared__ float sx[SCHUNK][HEADDIM];
    __shared__ float sB[SCHUNK][DSTATE];
    __shared__ float sC[SCHUNK][DSTATE];
    __shared__ float sdt[SCHUNK];
    __shared__ float sdA[SCHUNK];

    float h0 = 0.f, h1 = 0.f;
    const float Dv = Dp[h];

    for (int c0 = 0; c0 < SEQ; c0 += SCHUNK) {
        #pragma unroll
        for (int i = 0; i < 8; i++) {
            int idx = i * 512 + tid;
            int s = idx >> 6, p = idx & 63;
            int t = reverse ? (SEQ - 1 - (c0 + s)) : (c0 + s);
            sx[s][p] = conv[((size_t)(b * SEQ + t)) * CONVDIM + h * HEADDIM + p];
        }
        #pragma unroll
        for (int i = 0; i < 2; i++) {
            int idx = i * 512 + tid;
            int s = idx >> 4, nn = idx & 15;
            int t = reverse ? (SEQ - 1 - (c0 + s)) : (c0 + s);
            size_t base = ((size_t)(b * SEQ + t)) * CONVDIM;
            sB[s][nn] = conv[base + DINNER + nn];
            sC[s][nn] = conv[base + DINNER + DSTATE + nn];
        }
        if (tid < SCHUNK) {
            int t = reverse ? (SEQ - 1 - (c0 + tid)) : (c0 + tid);
            sdt[tid] = dt[(size_t)(b * SEQ + t) * NHEADS + h];
            sdA[tid] = dA[(size_t)(b * SEQ + t) * NHEADS + h];
        }
        __syncthreads();

        #pragma unroll 4
        for (int s = 0; s < SCHUNK; s++) {
            float dAv = sdA[s], dtv = sdt[s];
            float Bn = sB[s][n], Cn = sC[s][n];
            float x0 = sx[s][pp], x1 = sx[s][pp + 32];
            h0 = h0 * dAv + (dtv * x0) * Bn;
            h1 = h1 * dAv + (dtv * x1) * Bn;
            float y0 = h0 * Cn, y1 = h1 * Cn;
            #pragma unroll
            for (int m = 8; m >= 1; m >>= 1) {
                y0 += __shfl_xor_sync(0xffffffffu, y0, m);
                y1 += __shfl_xor_sync(0xffffffffu, y1, m);
            }
            if (n == 0) {
                int t = reverse ? (SEQ - 1 - (c0 + s)) : (c0 + s);
                size_t o = ((size_t)(b * SEQ + t)) * DINNER + h * HEADDIM;
                y[o + pp]      = y0 + Dv * x0;
                y[o + pp + 32] = y1 + Dv * x1;
            }
        }
        __syncthreads();
    }
}

// ---------------- gate (y * silu(z)) + grouped RMSNorm -> fp16 ----------------
__global__ __launch_bounds__(256) void gate_rmsnorm_kernel(
    const float* __restrict__ proj, const float* __restrict__ y_in,
    const float* __restrict__ norm_w, __half* __restrict__ y_out)
{
    int row = blockIdx.x;
    int tid = threadIdx.x;
    float v[6];
    float ss = 0.f;
    #pragma unroll
    for (int i = 0; i < 6; i++) {
        int c = tid + i * 256;
        float z  = proj[(size_t)row * DPROJP + c];
        float yv = y_in[(size_t)row * DINNER + c];
        float t = yv * silu(z);
        v[i] = t; ss += t * t;
    }
    float tot = block_reduce_sum(ss);
    float rs = rsqrtf(tot * (1.0f / DINNER) + 1e-5f);
    #pragma unroll
    for (int i = 0; i < 6; i++) {
        int c = tid + i * 256;
        y_out[(size_t)row * DINNER + c] = __float2half_rn(v[i] * rs * norm_w[c]);
    }
}

// ---------------- host-side input binding by element count ----------------
static const float* pick(void* const* d_in, const int* sz, int n_in, int count, int occ) {
    int seen = 0;
    for (int i = 0; i < n_in; i++) {
        if (sz[i] == count) {
            if (seen == occ) return (const float*)d_in[i];
            seen++;
        }
    }
    return nullptr;
}

extern "C" void kernel_launch(void* const* d_in, const int* in_sizes, int n_in,
                              void* d_out, int out_size)
{
    const float* x      = pick(d_in, in_sizes, n_in, NTOK * DMODEL, 0);
    const float* ln1_w  = pick(d_in, in_sizes, n_in, 768, 0);
    const float* ln1_b  = pick(d_in, in_sizes, n_in, 768, 1);
    const float* ln2_w  = pick(d_in, in_sizes, n_in, 768, 2);
    const float* ln2_b  = pick(d_in, in_sizes, n_in, 768, 3);
    const float* ffn_b2 = pick(d_in, in_sizes, n_in, 768, 4);
    const float* ffn_w1 = pick(d_in, in_sizes, n_in, DINNER * DFFN, 0);
    const float* ffn_b1 = pick(d_in, in_sizes, n_in, DFFN, 0);
    const float* ffn_w2 = pick(d_in, in_sizes, n_in, DFFN * DMODEL, 0);

    const float* in_w0    = pick(d_in, in_sizes, n_in, DMODEL * DPROJ, 0);
    const float* in_w1    = pick(d_in, in_sizes, n_in, DMODEL * DPROJ, 1);
    const float* conv_w0  = pick(d_in, in_sizes, n_in, CONVDIM * DCONV, 0);
    const float* conv_w1  = pick(d_in, in_sizes, n_in, CONVDIM * DCONV, 1);
    const float* conv_b0  = pick(d_in, in_sizes, n_in, CONVDIM, 0);
    const float* conv_b1  = pick(d_in, in_sizes, n_in, CONVDIM, 1);
    const float* dt_bias0 = pick(d_in, in_sizes, n_in, NHEADS, 0);
    const float* dt_bias1 = pick(d_in, in_sizes, n_in, NHEADS, 3);
    const float* A_log0   = pick(d_in, in_sizes, n_in, NHEADS, 1);
    const float* A_log1   = pick(d_in, in_sizes, n_in, NHEADS, 4);
    const float* Dp0      = pick(d_in, in_sizes, n_in, NHEADS, 2);
    const float* Dp1      = pick(d_in, in_sizes, n_in, NHEADS, 5);
    const float* norm_w0  = pick(d_in, in_sizes, n_in, DINNER, 0);
    const float* norm_w1  = pick(d_in, in_sizes, n_in, DINNER, 1);
    const float* out_w0   = pick(d_in, in_sizes, n_in, DINNER * DMODEL, 0);
    const float* out_w1   = pick(d_in, in_sizes, n_in, DINNER * DMODEL, 1);

    float* p_proj = 0;  cudaGetSymbolAddress((void**)&p_proj, g_proj);
    float* p_conv = 0;  cudaGetSymbolAddress((void**)&p_conv, g_conv);
    float* p_dt   = 0;  cudaGetSymbolAddress((void**)&p_dt,   g_dt);
    float* p_dA   = 0;  cudaGetSymbolAddress((void**)&p_dA,   g_dA);
    float* p_y    = 0;  cudaGetSymbolAddress((void**)&p_y,    g_y);
    float* p_bi   = 0;  cudaGetSymbolAddress((void**)&p_bi,   g_bi);
    float* p_ffn  = 0;  cudaGetSymbolAddress((void**)&p_ffn,  g_ffn);
    float* p_h2   = 0;  cudaGetSymbolAddress((void**)&p_h2,   g_h2);

    __half* ph_xn  = 0; cudaGetSymbolAddress((void**)&ph_xn,  h_xn);
    __half* ph_yg  = 0; cudaGetSymbolAddress((void**)&ph_yg,  h_yg);
    __half* ph_bi  = 0; cudaGetSymbolAddress((void**)&ph_bi,  h_bi);
    __half* ph_ffn = 0; cudaGetSymbolAddress((void**)&ph_ffn, h_ffn);

    __half* pw_in0  = 0; cudaGetSymbolAddress((void**)&pw_in0,  hw_in0);
    __half* pw_in1  = 0; cudaGetSymbolAddress((void**)&pw_in1,  hw_in1);
    __half* pw_out0 = 0; cudaGetSymbolAddress((void**)&pw_out0, hw_out0);
    __half* pw_out1 = 0; cudaGetSymbolAddress((void**)&pw_out1, hw_out1);
    __half* pw_f1   = 0; cudaGetSymbolAddress((void**)&pw_f1,   hw_f1);
    __half* pw_f2   = 0; cudaGetSymbolAddress((void**)&pw_f2,   hw_f2);

    float* out = (float*)d_out;
    const int T = 256;

    // 0) weight conversion fp32 -> fp16
    {
        int n;
        n = DMODEL * DPROJ / 4;
        f2h_kernel<<<(n + T - 1) / T, T>>>(in_w0, pw_in0, n);
        f2h_kernel<<<(n + T - 1) / T, T>>>(in_w1, pw_in1, n);
        n = DINNER * DMODEL / 4;
        f2h_kernel<<<(n + T - 1) / T, T>>>(out_w0, pw_out0, n);
        f2h_kernel<<<(n + T - 1) / T, T>>>(out_w1, pw_out1, n);
        n = DINNER * DFFN / 4;
        f2h_kernel<<<(n + T - 1) / T, T>>>(ffn_w1, pw_f1, n);
        n = DFFN * DMODEL / 4;
        f2h_kernel<<<(n + T - 1) / T, T>>>(ffn_w2, pw_f2, n);
    }

    // 1) LN1 -> fp16 activations
    layernorm_kernel<<<NTOK, 256>>>(x, nullptr, ln1_w, ln1_b, nullptr, ph_xn);

    // 2) two mamba directions
    for (int dir = 0; dir < 2; dir++) {
        const __half* w_in   = (dir == 0) ? pw_in0  : pw_in1;
        const __half* w_out  = (dir == 0) ? pw_out0 : pw_out1;
        const float*  cwp    = (dir == 0) ? conv_w0 : conv_w1;
        const float*  cbp    = (dir == 0) ? conv_b0 : conv_b1;
        const float*  dtb    = (dir == 0) ? dt_bias0 : dt_bias1;
        const float*  alog   = (dir == 0) ? A_log0  : A_log1;
        const float*  dpp    = (dir == 0) ? Dp0     : Dp1;
        const float*  nwp    = (dir == 0) ? norm_w0 : norm_w1;

        // in_proj: [8192,768] @ [768,3128] -> fp32 proj (padded ldc 3200)
        {
            dim3 grid(DPROJP / BN, NTOK / BM);
            hgemm_wmma<<<grid, 256>>>(ph_xn, w_in, p_proj, NTOK, DPROJ, DMODEL, DPROJP, 0);
        }
        dtda_kernel<<<(NTOK * NHEADS + T - 1) / T, T>>>(p_proj, dtb, alog, p_dt, p_dA);
        conv_kernel<<<(NTOK * CONVDIM + T - 1) / T, T>>>(p_proj, cwp, cbp, p_conv, dir);
        scan_kernel<<<BATCH * NHEADS, 512>>>(p_conv, p_dt, p_dA, dpp, p_y, dir);
        gate_rmsnorm_kernel<<<NTOK, 256>>>(p_proj, p_y, nwp, ph_yg);
        // out_proj: [8192,1536] @ [1536,768] -> fp32 bi at column offset dir*768
        {
            dim3 grid(DMODEL / BN, NTOK / BM);
            hgemm_wmma<<<grid, 256>>>(ph_yg, w_out, p_bi, NTOK, DMODEL, DINNER, DINNER, dir * DMODEL);
        }
    }

    // convert bi fp32 -> fp16
    {
        int n = NTOK * DINNER / 4;
        f2h_kernel<<<(n + T - 1) / T, T>>>(p_bi, ph_bi, n);
    }

    // 3) FFN1 GEMM then bias+gelu -> fp16
    {
        dim3 grid(DFFN / BN, NTOK / BM);
        hgemm_wmma<<<grid, 256>>>(ph_bi, pw_f1, p_ffn, NTOK, DFFN, DINNER, DFFN, 0);
        int n = NTOK * DFFN;
        bias_gelu_kernel<<<(n + T - 1) / T, T>>>(p_ffn, ffn_b1, nullptr, ph_ffn, DFFN, n);
    }
    // 4) FFN2 GEMM then bias+gelu -> fp32
    {
        dim3 grid(DMODEL / BN, NTOK / BM);
        hgemm_wmma<<<grid, 256>>>(ph_ffn, pw_f2, p_h2, NTOK, DMODEL, DFFN, DMODEL, 0);
        int n = NTOK * DMODEL;
        bias_gelu_kernel<<<(n + T - 1) / T, T>>>(p_h2, ffn_b2, p_h2, nullptr, DMODEL, n);
    }
    // 5) out = LN2(x + h)
    layernorm_kernel<<<NTOK, 256>>>(x, p_h2, ln2_w, ln2_b, out, nullptr);
}